// round 13
// baseline (speedup 1.0000x reference)
#include <cuda_runtime.h>
#include <cstdint>

#define MAXDISP 192
#define HH      192
#define WW      384
#define WD      (WW + MAXDISP - 1)   /* 575 */
#define HW      (HH * WW)            /* 73728 */

#define NCHUNK 4                     /* d-chunks */
#define DPC    (MAXDISP / NCHUNK)    /* 48 */
#define NT     768                   /* kernel-1 threads = 2 views x 384 px */
#define S      5                     /* pipeline stages */
#define RQ     146                   /* float4 per channel row (584 floats) */
#define ROWF   (4 * RQ)              /* 584 floats */

// v layout: [1][4][D][H][WD]  ch 0 = logits, ch 1..3 = color
// out layout: color_1[3*HW] | color_2[3*HW] | disp_1[HW] | disp_2[HW]
// partials: [chunk][h][view][val][w]  val: 0=l 1=a_d 2..4=a_c  (11.8 MB)
__device__ float g_part[NCHUNK][HH][2][5][WW];

__device__ __forceinline__ void cp16(uint32_t dst, const float* src) {
    asm volatile("cp.async.cg.shared.global [%0], [%1], 16;" :: "r"(dst), "l"(src));
}
__device__ __forceinline__ void cpa_commit() {
    asm volatile("cp.async.commit_group;" ::: "memory");
}
__device__ __forceinline__ void cpa_wait3() {
    asm volatile("cp.async.wait_group %0;" :: "n"(S - 2) : "memory");
}

__global__ __launch_bounds__(NT, 2)
void vr_main_kernel(const float* __restrict__ v) {
    const int tid   = threadIdx.x;
    const int h     = blockIdx.x >> 2;
    const int chunk = blockIdx.x & 3;
    const int d0    = chunk * DPC;
    const int a     = (3 * h) & 3;          // row base misalignment (floats)

    const int stride_d = HH * WD;            // 110400
    const int stride_c = MAXDISP * HH * WD;  // 21196800

    // aligned base of this h row (channel 0); h*WD - a is divisible by 4
    const float* __restrict__ rowbase0 = v + h * WD - a;

    // staged rows: [stage][ch][584 floats]; 46720 B static smem
    __shared__ __align__(16) float buf[S][4][ROWF];

    const uint32_t sbase = (uint32_t)__cvta_generic_to_shared(&buf[0][0][0]);

    const int view = (tid >= WW) ? 1 : 0;
    const int px   = view ? (tid - WW) : tid;

    float l = 0.f, ad = 0.f, ac0 = 0.f, ac1 = 0.f, ac2 = 0.f;

    // ---- prologue: issue stages 0..S-2 (groups 0..S-2, group j = stage j) ----
    #pragma unroll
    for (int s = 0; s < S - 1; ++s) {
        const int d     = d0 + s;
        const int ncols = WD - d;                 // cols needed: [0, 575-d)
        const int nq    = (a + ncols + 3) >> 2;   // float4 count per channel
        const float* rb = rowbase0 + d * stride_d;
        if (tid < 4 * nq) {
            const int ch = tid / nq;
            const int q  = tid - ch * nq;
            cp16(sbase + ((s * 4 + ch) * ROWF + 4 * q) * 4, rb + ch * stride_c + 4 * q);
        }
        cpa_commit();
    }

    // ---- main loop ----
    // invariant: at top of iter i, committed groups = (S-1)+i; wait(S-2)
    // leaves <= S-2 pending => groups 0..i complete => stage i resident.
    for (int i = 0; i < DPC; ++i) {
        cpa_wait3();
        __syncthreads();          // cross-thread visibility of staged bytes

        const int slot = i % S;
        const int d    = d0 + i;
        const int sh   = MAXDISP - 1 - d;
        const int col  = a + px + (view ? sh : 0);   // < a + ncols

        const float b  = buf[slot][0][col];
        const float q0 = buf[slot][1][col];
        const float q1 = buf[slot][2][col];
        const float q2 = buf[slot][3][col];

        // no max-subtraction: logits ~ N(0,1); exp cannot overflow fp32 and the
        // softmax ratio is shift-invariant; partials are linear -> splittable.
        const float e  = __expf(b);
        const float dv = (float)sh;

        l   += e;
        ad   = fmaf(e, dv, ad);
        ac0  = fmaf(e, q0, ac0);
        ac1  = fmaf(e, q1, ac1);
        ac2  = fmaf(e, q2, ac2);

        __syncthreads();          // all reads of the recycled slot done

        const int nxt = i + S - 1;
        if (nxt < DPC) {
            const int dn    = d0 + nxt;
            const int ncols = WD - dn;
            const int nq    = (a + ncols + 3) >> 2;
            const int nslot = nxt % S;
            const float* rb = rowbase0 + dn * stride_d;
            if (tid < 4 * nq) {
                const int ch = tid / nq;
                const int q  = tid - ch * nq;
                cp16(sbase + ((nslot * 4 + ch) * ROWF + 4 * q) * 4,
                     rb + ch * stride_c + 4 * q);
            }
        }
        cpa_commit();   // UNCONDITIONAL: keeps group count uniform (tail fix)
    }

    // write partials: coalesced over px
    g_part[chunk][h][view][0][px] = l;
    g_part[chunk][h][view][1][px] = ad;
    g_part[chunk][h][view][2][px] = ac0;
    g_part[chunk][h][view][3][px] = ac1;
    g_part[chunk][h][view][4][px] = ac2;
}

__global__ __launch_bounds__(128)
void vr_reduce_kernel(float* __restrict__ out) {
    const int pix = blockIdx.x * 128 + threadIdx.x;
    if (pix >= HW) return;
    const int h = pix / WW;
    const int w = pix % WW;

    float s[2][5];
    #pragma unroll
    for (int vw = 0; vw < 2; ++vw)
        #pragma unroll
        for (int t = 0; t < 5; ++t) s[vw][t] = 0.f;

    #pragma unroll
    for (int c = 0; c < NCHUNK; ++c)
        #pragma unroll
        for (int vw = 0; vw < 2; ++vw)
            #pragma unroll
            for (int t = 0; t < 5; ++t)
                s[vw][t] += g_part[c][h][vw][t][w];

    const float r1 = 1.0f / s[0][0];
    const float r2 = 1.0f / s[1][0];

    out[0 * HW + pix] = s[0][2] * r1;   // color_1
    out[1 * HW + pix] = s[0][3] * r1;
    out[2 * HW + pix] = s[0][4] * r1;
    out[3 * HW + pix] = s[1][2] * r2;   // color_2
    out[4 * HW + pix] = s[1][3] * r2;
    out[5 * HW + pix] = s[1][4] * r2;
    out[6 * HW + pix] = s[0][1] * r1;   // disp_1
    out[7 * HW + pix] = s[1][1] * r2;   // disp_2
}

extern "C" void kernel_launch(void* const* d_in, const int* in_sizes, int n_in,
                              void* d_out, int out_size) {
    const float* v = (const float*)d_in[0];
    float* out = (float*)d_out;

    vr_main_kernel<<<HH * NCHUNK, NT>>>(v);            // 768 blocks x 768 thr
    vr_reduce_kernel<<<(HW + 127) / 128, 128>>>(out);  // 576 blocks
}

// round 14
// speedup vs baseline: 1.4961x; 1.4961x over previous
#include <cuda_runtime.h>

#define MAXDISP 192
#define HH      192
#define WW      384
#define WD      (WW + MAXDISP - 1)   /* 575 */
#define HW      (HH * WW)            /* 73728 */

#define NCHUNK 2                     /* D-chunks */
#define DPC    (MAXDISP / NCHUNK)    /* 96 disparities per chunk */
#define PIXB   64                    /* pixels per block: lane and lane+32 */

// v layout: [1][4][D][H][WD]  ch 0 = logits, ch 1..3 = color
// out layout: color_1[3*HW] | color_2[3*HW] | disp_1[HW] | disp_2[HW]
// warp = (part, chunk, view): part0 accumulates l/ad/c0; part1 accumulates c1/c2

__global__ __launch_bounds__(256, 8)
void volume_render_v8_kernel(const float* __restrict__ v, float* __restrict__ out) {
    const int lane  = threadIdx.x & 31;
    const int warp  = threadIdx.x >> 5;
    const int view  = warp & 1;           // 0: col=w, 1: col=w+shift
    const int chunk = (warp >> 1) & 1;    // 0..1
    const int part  = warp >> 2;          // 0: {l,ad,c0}  1: {c1,c2}

    const int pix0 = blockIdx.x * PIXB;   // 384 % 64 == 0 -> block stays in one row
    const int h    = pix0 / WW;
    const int w0   = pix0 % WW;

    const int stride_d = HH * WD;            // 110400
    const int stride_c = MAXDISP * HH * WD;  // 21196800

    const int d0   = chunk * DPC;
    const int sh0  = view ? (MAXDISP - 1 - d0) : 0;
    const int step = stride_d - view;        // view2 shift shrinks by 1 per d

    // pixel A = w0+lane, pixel B = w0+lane+32 -> 256B contiguous per stream
    const float* __restrict__ p = v + d0 * stride_d + h * WD + w0 + lane + sh0;

    // red[view][chunk][val][px]  val: 0=l 1=ad 2=c0 3=c1 4=c2
    __shared__ float red[2][NCHUNK][5][PIXB];
    __shared__ float fin[2][5][PIXB];

    if (part == 0) {
        float lA = 0.f, lB = 0.f, adA = 0.f, adB = 0.f, c0A = 0.f, c0B = 0.f;
        float dv = (float)(MAXDISP - 1 - d0);

        #pragma unroll 4
        for (int i = 0; i < DPC; ++i) {
            const float bA = p[0];
            const float bB = p[32];
            const float qA = p[stride_c];
            const float qB = p[stride_c + 32];

            // no max-subtraction: logits ~ N(0,1); exp cannot overflow fp32 and
            // the softmax ratio is shift-invariant; partials are linear.
            const float eA = __expf(bA);
            const float eB = __expf(bB);

            lA  += eA;                    lB  += eB;
            adA  = fmaf(eA, dv, adA);     adB  = fmaf(eB, dv, adB);
            c0A  = fmaf(eA, qA, c0A);     c0B  = fmaf(eB, qB, c0B);

            p  += step;
            dv -= 1.0f;
        }
        red[view][chunk][0][lane] = lA;   red[view][chunk][0][lane + 32] = lB;
        red[view][chunk][1][lane] = adA;  red[view][chunk][1][lane + 32] = adB;
        red[view][chunk][2][lane] = c0A;  red[view][chunk][2][lane + 32] = c0B;
    } else {
        float c1A = 0.f, c1B = 0.f, c2A = 0.f, c2B = 0.f;

        #pragma unroll 4
        for (int i = 0; i < DPC; ++i) {
            const float bA  = p[0];
            const float bB  = p[32];
            const float q1A = p[2 * stride_c];
            const float q1B = p[2 * stride_c + 32];
            const float q2A = p[3 * stride_c];
            const float q2B = p[3 * stride_c + 32];

            const float eA = __expf(bA);   // recomputed; logit rows hit L2
            const float eB = __expf(bB);

            c1A = fmaf(eA, q1A, c1A);     c1B = fmaf(eB, q1B, c1B);
            c2A = fmaf(eA, q2A, c2A);     c2B = fmaf(eB, q2B, c2B);

            p += step;
        }
        red[view][chunk][3][lane] = c1A;  red[view][chunk][3][lane + 32] = c1B;
        red[view][chunk][4][lane] = c2A;  red[view][chunk][4][lane + 32] = c2B;
    }
    __syncthreads();

    // reduce over chunks: fin[view][val][px], 640 tasks over 256 threads
    for (int t = threadIdx.x; t < 2 * 5 * PIXB; t += 256) {
        const int vw  = t / (5 * PIXB);
        const int val = (t / PIXB) % 5;
        const int px  = t & 63;
        fin[vw][val][px] = red[vw][0][val][px] + red[vw][1][val][px];
    }
    __syncthreads();

    // 8 outputs x 64 px = 512 tasks over 256 threads
    // outv 0-2: color_1 ; 3-5: color_2 ; 6: disp_1 ; 7: disp_2
    for (int t = threadIdx.x; t < 8 * PIXB; t += 256) {
        const int outv = t >> 6;
        const int px   = t & 63;
        const int vw   = (outv < 3) ? 0 : (outv < 6 ? 1 : (outv - 6));
        const int val  = (outv < 6) ? (2 + outv - vw * 3) : 1;
        out[outv * HW + pix0 + px] = fin[vw][val][px] / fin[vw][0][px];
    }
}

extern "C" void kernel_launch(void* const* d_in, const int* in_sizes, int n_in,
                              void* d_out, int out_size) {
    const float* v = (const float*)d_in[0];
    float* out = (float*)d_out;

    const int blocks = HW / PIXB;   // 1152
    volume_render_v8_kernel<<<blocks, 256>>>(v, out);
}